// round 1
// baseline (speedup 1.0000x reference)
#include <cuda_runtime.h>

#define Bn 8
#define Ln 2500
#define Dn 512
#define Yn 8921
#define LT 64      // l-tile rows
#define YT 128     // y-tile cols (labels)
#define KC 32      // k chunk
#define NT 256     // threads per block

// packed fp32x2 helpers (sm_100+ f32x2 pipe; ptxas never auto-fuses these)
__device__ __forceinline__ unsigned long long dup2(float v) {
    unsigned long long r;
    unsigned int u = __float_as_uint(v);
    asm("mov.b64 %0, {%1, %1};" : "=l"(r) : "r"(u));
    return r;
}
__device__ __forceinline__ void ffma2(unsigned long long& d,
                                      unsigned long long a,
                                      unsigned long long b) {
    asm("fma.rn.f32x2 %0, %1, %2, %0;" : "+l"(d) : "l"(a), "l"(b));
}

// Fused: S = U_w @ x^T, T = final_w @ x^T, y = sum_l softmax(S)*T + b
// One block = (batch b, 128-label tile). Loops over L in 64-row tiles,
// K in 32-wide chunks. Per-thread: 4 l x 8 y, dual (S,T) accumulators
// held as f32x2 pairs. Softmax done without max-subtraction: scores are
// ~N(0,1) (|S| < ~8), exp() cannot overflow, math identical to reference.
__global__ __launch_bounds__(NT, 2)
void attn_fused_kernel(const float* __restrict__ x,
                       const float* __restrict__ U_w,
                       const float* __restrict__ F_w,
                       const float* __restrict__ f_b,
                       float* __restrict__ out)
{
    __shared__ __align__(16) float xs[KC][LT];       // 8 KB
    __shared__ __align__(16) float ws[2][KC][YT];    // 32 KB

    const int tid   = threadIdx.x;
    const int b     = blockIdx.y;
    const int y0    = blockIdx.x * YT;
    const int gy    = tid & 15;      // 16 col groups
    const int gl    = tid >> 4;      // 16 row groups
    const int ybase = gy * 8;        // 8 labels per thread
    const int lbase = gl * 4;        // 4 l-rows per thread

    // running softmax accumulators per owned label (denominator, numerator)
    float ssum[8], zsum[8];
    #pragma unroll
    for (int j = 0; j < 8; j++) { ssum[j] = 0.f; zsum[j] = 0.f; }

    const float* xb = x + (size_t)b * Ln * Dn;

    for (int l0 = 0; l0 < Ln; l0 += LT) {
        unsigned long long aS[4][4], aT[4][4];  // [l][ypair]
        #pragma unroll
        for (int i = 0; i < 4; i++)
            #pragma unroll
            for (int j = 0; j < 4; j++) { aS[i][j] = 0ull; aT[i][j] = 0ull; }

        for (int k0 = 0; k0 < Dn; k0 += KC) {
            __syncthreads();
            // ---- stage x tile [LT x KC] -> xs[k][l] (transposed) ----
            #pragma unroll
            for (int it = 0; it < (LT * KC / 4) / NT; it++) {   // 2 iters
                int idx = tid + it * NT;
                int row = idx >> 3;           // 8 float4 per l-row
                int c4  = (idx & 7) * 4;
                float4 v = make_float4(0.f, 0.f, 0.f, 0.f);
                int lg = l0 + row;
                if (lg < Ln)
                    v = *(const float4*)(xb + (size_t)lg * Dn + k0 + c4);
                xs[c4 + 0][row] = v.x; xs[c4 + 1][row] = v.y;
                xs[c4 + 2][row] = v.z; xs[c4 + 3][row] = v.w;
            }
            // ---- stage both weight tiles [YT x KC] -> ws[m][k][y] ----
            #pragma unroll
            for (int m = 0; m < 2; m++) {
                const float* W = m ? F_w : U_w;
                #pragma unroll
                for (int it = 0; it < (YT * KC / 4) / NT; it++) { // 4 iters
                    int idx = tid + it * NT;
                    int row = idx >> 3;
                    int c4  = (idx & 7) * 4;
                    float4 v = make_float4(0.f, 0.f, 0.f, 0.f);
                    int yg = y0 + row;
                    if (yg < Yn)
                        v = *(const float4*)(W + (size_t)yg * Dn + k0 + c4);
                    ws[m][c4 + 0][row] = v.x; ws[m][c4 + 1][row] = v.y;
                    ws[m][c4 + 2][row] = v.z; ws[m][c4 + 3][row] = v.w;
                }
            }
            __syncthreads();

            // ---- f32x2 dual-GEMM inner loop ----
            #pragma unroll 8
            for (int k = 0; k < KC; k++) {
                float4 xv = *(const float4*)&xs[k][lbase];   // broadcast across warp
                unsigned long long xd[4];
                xd[0] = dup2(xv.x); xd[1] = dup2(xv.y);
                xd[2] = dup2(xv.z); xd[3] = dup2(xv.w);
                const ulonglong2* up = (const ulonglong2*)&ws[0][k][ybase];
                const ulonglong2* fp = (const ulonglong2*)&ws[1][k][ybase];
                ulonglong2 u01 = up[0], u23 = up[1];
                ulonglong2 f01 = fp[0], f23 = fp[1];
                unsigned long long wu[4] = {u01.x, u01.y, u23.x, u23.y};
                unsigned long long wf[4] = {f01.x, f01.y, f23.x, f23.y};
                #pragma unroll
                for (int i = 0; i < 4; i++) {
                    #pragma unroll
                    for (int j = 0; j < 4; j++) {
                        ffma2(aS[i][j], xd[i], wu[j]);
                        ffma2(aT[i][j], xd[i], wf[j]);
                    }
                }
            }
        }

        // ---- per-l-tile softmax accumulation (registers only) ----
        #pragma unroll
        for (int i = 0; i < 4; i++) {
            int lg = l0 + lbase + i;
            if (lg < Ln) {
                #pragma unroll
                for (int j = 0; j < 4; j++) {
                    float2 sv = *(float2*)&aS[i][j];
                    float2 tv = *(float2*)&aT[i][j];
                    float e0 = __expf(sv.x);
                    float e1 = __expf(sv.y);
                    ssum[2 * j + 0] += e0; zsum[2 * j + 0] += e0 * tv.x;
                    ssum[2 * j + 1] += e1; zsum[2 * j + 1] += e1 * tv.y;
                }
            }
        }
    }

    // ---- final cross-thread reduction (reuse ws smem; deterministic) ----
    __syncthreads();
    float* reds = &ws[0][0][0];        // 16 x YT floats
    float* redz = reds + 16 * YT;      // next 16 x YT floats (fits in ws[0])
    #pragma unroll
    for (int j = 0; j < 8; j++) {
        reds[gl * YT + ybase + j] = ssum[j];
        redz[gl * YT + ybase + j] = zsum[j];
    }
    __syncthreads();
    if (tid < YT) {
        int yg = y0 + tid;
        if (yg < Yn) {
            float s = 0.f, z = 0.f;
            #pragma unroll
            for (int i = 0; i < 16; i++) {
                s += reds[i * YT + tid];
                z += redz[i * YT + tid];
            }
            out[(size_t)b * Yn + yg] = z / s + f_b[yg];
        }
    }
}

// mean BCE-with-logits over the y just written to d_out. Single block,
// fixed-order tree reduction -> deterministic.
__global__ void bce_kernel(const float* __restrict__ y,
                           const float* __restrict__ t,
                           float* __restrict__ loss_out, int n)
{
    __shared__ float red[256];
    float acc = 0.f;
    for (int i = threadIdx.x; i < n; i += 256) {
        float v  = y[i];
        float tt = t[i];
        acc += fmaxf(v, 0.f) - v * tt + log1pf(__expf(-fabsf(v)));
    }
    red[threadIdx.x] = acc;
    __syncthreads();
    for (int s = 128; s > 0; s >>= 1) {
        if (threadIdx.x < s) red[threadIdx.x] += red[threadIdx.x + s];
        __syncthreads();
    }
    if (threadIdx.x == 0) loss_out[0] = red[0] / (float)n;
}

extern "C" void kernel_launch(void* const* d_in, const int* in_sizes, int n_in,
                              void* d_out, int out_size)
{
    const float* x      = (const float*)d_in[0];
    const float* target = (const float*)d_in[1];
    // d_in[2] = text_inputs (unused scalar)
    const float* U_w    = (const float*)d_in[3];
    const float* F_w    = (const float*)d_in[4];
    const float* f_b    = (const float*)d_in[5];
    float* out = (float*)d_out;

    dim3 grid((Yn + YT - 1) / YT, Bn);   // 70 x 8 blocks
    attn_fused_kernel<<<grid, NT>>>(x, U_w, F_w, f_b, out);

    if (out_size > Bn * Yn)
        bce_kernel<<<1, 256>>>(out, target, out + Bn * Yn, Bn * Yn);
}

// round 2
// speedup vs baseline: 1.6531x; 1.6531x over previous
#include <cuda_runtime.h>

#define Bn 8
#define Ln 2500
#define Dn 512
#define Yn 8921
#define LT 128     // l-tile rows per block
#define YT 128     // y-tile cols per block
#define KC 32      // k chunk
#define NT 256     // threads per block
#define TL 8       // l per thread
#define TY 8       // y per thread (4 f32x2 pairs)

// packed fp32x2 helpers (sm_100+ f32x2 pipe; ptxas never auto-fuses these)
__device__ __forceinline__ unsigned long long dup2(float v) {
    unsigned long long r;
    unsigned int u = __float_as_uint(v);
    asm("mov.b64 %0, {%1, %1};" : "=l"(r) : "r"(u));
    return r;
}
__device__ __forceinline__ void ffma2(unsigned long long& d,
                                      unsigned long long a,
                                      unsigned long long b) {
    asm("fma.rn.f32x2 %0, %1, %2, %0;" : "+l"(d) : "l"(a), "l"(b));
}

// Fused: S = U_w @ x^T, T = final_w @ x^T, y = sum_l softmax(S)*T + b.
// One block = (batch b, 128-label tile) x 128-l tile loop.
// Per-thread register tile: 8 l x 8 y, dual (S,T) f32x2 accumulators
// -> 128 FMA / 96 LDS-bytes per k per thread: FMA-pipe bound.
__global__ __launch_bounds__(NT)
void attn_fused_kernel(const float* __restrict__ x,
                       const float* __restrict__ U_w,
                       const float* __restrict__ F_w,
                       const float* __restrict__ f_b,
                       float* __restrict__ out)
{
    __shared__ __align__(16) float xs[KC][LT];       // 16 KB
    __shared__ __align__(16) float ws[2][KC][YT];    // 32 KB

    const int tid   = threadIdx.x;
    const int b     = blockIdx.y;
    const int y0    = blockIdx.x * YT;
    const int gy    = tid & 15;      // 16 col groups
    const int gl    = tid >> 4;      // 16 row groups
    const int ybase = gy * TY;       // 8 labels per thread
    const int lbase = gl * TL;       // 8 l-rows per thread

    // running softmax accumulators per owned label (denominator, numerator)
    float ssum[TY], zsum[TY];
    #pragma unroll
    for (int j = 0; j < TY; j++) { ssum[j] = 0.f; zsum[j] = 0.f; }

    const float* xb = x + (size_t)b * Ln * Dn;

    for (int l0 = 0; l0 < Ln; l0 += LT) {
        unsigned long long aS[TL][4], aT[TL][4];  // [l][ypair]
        #pragma unroll
        for (int i = 0; i < TL; i++)
            #pragma unroll
            for (int j = 0; j < 4; j++) { aS[i][j] = 0ull; aT[i][j] = 0ull; }

        for (int k0 = 0; k0 < Dn; k0 += KC) {
            __syncthreads();
            // ---- stage x tile [LT x KC] -> xs[k][l] (transposed) ----
            #pragma unroll
            for (int it = 0; it < (LT * KC / 4) / NT; it++) {   // 4 iters
                int idx = tid + it * NT;
                int row = idx >> 3;           // 8 float4 per l-row
                int c4  = (idx & 7) * 4;
                float4 v = make_float4(0.f, 0.f, 0.f, 0.f);
                int lg = l0 + row;
                if (lg < Ln)
                    v = *(const float4*)(xb + (size_t)lg * Dn + k0 + c4);
                xs[c4 + 0][row] = v.x; xs[c4 + 1][row] = v.y;
                xs[c4 + 2][row] = v.z; xs[c4 + 3][row] = v.w;
            }
            // ---- stage both weight tiles [YT x KC] -> ws[m][k][y] ----
            #pragma unroll
            for (int m = 0; m < 2; m++) {
                const float* W = m ? F_w : U_w;
                #pragma unroll
                for (int it = 0; it < (YT * KC / 4) / NT; it++) { // 4 iters
                    int idx = tid + it * NT;
                    int row = idx >> 3;
                    int c4  = (idx & 7) * 4;
                    float4 v = make_float4(0.f, 0.f, 0.f, 0.f);
                    int yg = y0 + row;
                    if (yg < Yn)
                        v = *(const float4*)(W + (size_t)yg * Dn + k0 + c4);
                    ws[m][c4 + 0][row] = v.x; ws[m][c4 + 1][row] = v.y;
                    ws[m][c4 + 2][row] = v.z; ws[m][c4 + 3][row] = v.w;
                }
            }
            __syncthreads();

            // ---- f32x2 dual-GEMM inner loop: 8l x 8y x 2mat per k ----
            #pragma unroll 4
            for (int k = 0; k < KC; k++) {
                float4 xv0 = *(const float4*)&xs[k][lbase];
                float4 xv1 = *(const float4*)&xs[k][lbase + 4];
                unsigned long long xd[TL];
                xd[0] = dup2(xv0.x); xd[1] = dup2(xv0.y);
                xd[2] = dup2(xv0.z); xd[3] = dup2(xv0.w);
                xd[4] = dup2(xv1.x); xd[5] = dup2(xv1.y);
                xd[6] = dup2(xv1.z); xd[7] = dup2(xv1.w);
                const ulonglong2* up = (const ulonglong2*)&ws[0][k][ybase];
                const ulonglong2* fp = (const ulonglong2*)&ws[1][k][ybase];
                ulonglong2 u01 = up[0], u23 = up[1];
                ulonglong2 f01 = fp[0], f23 = fp[1];
                unsigned long long wu[4] = {u01.x, u01.y, u23.x, u23.y};
                unsigned long long wf[4] = {f01.x, f01.y, f23.x, f23.y};
                #pragma unroll
                for (int i = 0; i < TL; i++) {
                    #pragma unroll
                    for (int j = 0; j < 4; j++) {
                        ffma2(aS[i][j], xd[i], wu[j]);
                        ffma2(aT[i][j], xd[i], wf[j]);
                    }
                }
            }
        }

        // ---- per-l-tile softmax accumulation (registers only) ----
        #pragma unroll
        for (int i = 0; i < TL; i++) {
            int lg = l0 + lbase + i;
            if (lg < Ln) {
                #pragma unroll
                for (int j = 0; j < 4; j++) {
                    float2 sv = *(float2*)&aS[i][j];
                    float2 tv = *(float2*)&aT[i][j];
                    float e0 = __expf(sv.x);
                    float e1 = __expf(sv.y);
                    ssum[2 * j + 0] += e0; zsum[2 * j + 0] += e0 * tv.x;
                    ssum[2 * j + 1] += e1; zsum[2 * j + 1] += e1 * tv.y;
                }
            }
        }
    }

    // ---- final cross-thread reduction (reuse ws smem; deterministic) ----
    __syncthreads();
    float* reds = &ws[0][0][0];        // 16 x YT floats (8 KB)
    float* redz = reds + 16 * YT;      // next 16 x YT floats (8 KB)
    #pragma unroll
    for (int j = 0; j < TY; j++) {
        reds[gl * YT + ybase + j] = ssum[j];
        redz[gl * YT + ybase + j] = zsum[j];
    }
    __syncthreads();
    if (tid < YT) {
        int yg = y0 + tid;
        if (yg < Yn) {
            float s = 0.f, z = 0.f;
            #pragma unroll
            for (int i = 0; i < 16; i++) {
                s += reds[i * YT + tid];
                z += redz[i * YT + tid];
            }
            out[(size_t)b * Yn + yg] = z / s + f_b[yg];
        }
    }
}

// mean BCE-with-logits over the y just written to d_out. Single block,
// fixed-order tree reduction -> deterministic.
__global__ void bce_kernel(const float* __restrict__ y,
                           const float* __restrict__ t,
                           float* __restrict__ loss_out, int n)
{
    __shared__ float red[1024];
    float acc = 0.f;
    for (int i = threadIdx.x; i < n; i += 1024) {
        float v  = y[i];
        float tt = t[i];
        acc += fmaxf(v, 0.f) - v * tt + log1pf(__expf(-fabsf(v)));
    }
    red[threadIdx.x] = acc;
    __syncthreads();
    for (int s = 512; s > 0; s >>= 1) {
        if (threadIdx.x < s) red[threadIdx.x] += red[threadIdx.x + s];
        __syncthreads();
    }
    if (threadIdx.x == 0) loss_out[0] = red[0] / (float)n;
}

extern "C" void kernel_launch(void* const* d_in, const int* in_sizes, int n_in,
                              void* d_out, int out_size)
{
    const float* x      = (const float*)d_in[0];
    const float* target = (const float*)d_in[1];
    // d_in[2] = text_inputs (unused scalar)
    const float* U_w    = (const float*)d_in[3];
    const float* F_w    = (const float*)d_in[4];
    const float* f_b    = (const float*)d_in[5];
    float* out = (float*)d_out;

    dim3 grid((Yn + YT - 1) / YT, Bn);   // 70 x 8 = 560 blocks
    attn_fused_kernel<<<grid, NT>>>(x, U_w, F_w, f_b, out);

    if (out_size > Bn * Yn)
        bce_kernel<<<1, 1024>>>(out, target, out + Bn * Yn, Bn * Yn);
}

// round 5
// speedup vs baseline: 4.3319x; 2.6204x over previous
#include <cuda_runtime.h>
#include <cuda_bf16.h>
#include <cstdint>

#define Bn 8
#define Ln 2500
#define Dn 512
#define Yn 8921
#define YT 128          // y per CTA
#define LT 128          // l per CTA tile
#define KC 32           // k per chunk (bf16 elems)
#define NCH (Dn / KC)   // 16 chunks
#define NTILES 20       // ceil(2500/128)
#define NT 256
#define SW 20                   // smem row stride in words (16 data + 4 pad)
#define TILEW (128 * SW)        // words per staged tile (2560)
#define BUFW (6 * TILEW)        // Uh Ul Fh Fl Xh Xl
#define SMEM_BYTES (2 * BUFW * 4)   // 122880

// bf16 hi/lo scratch (device globals; no runtime alloc)
__device__ __nv_bfloat16 g_xh[(size_t)Bn * Ln * Dn];
__device__ __nv_bfloat16 g_xl[(size_t)Bn * Ln * Dn];
__device__ __nv_bfloat16 g_uh[(size_t)Yn * Dn];
__device__ __nv_bfloat16 g_ul[(size_t)Yn * Dn];
__device__ __nv_bfloat16 g_fh[(size_t)Yn * Dn];
__device__ __nv_bfloat16 g_fl[(size_t)Yn * Dn];

// mma.sync m16n8k16 bf16 (plain sm_80+ instruction, compiles at compute_103)
#define MMA(D, A, B0, B1)                                                   \
    asm volatile(                                                           \
        "mma.sync.aligned.m16n8k16.row.col.f32.bf16.bf16.f32 "              \
        "{%0,%1,%2,%3}, {%4,%5,%6,%7}, {%8,%9}, {%0,%1,%2,%3};"             \
        : "+f"((D)[0]), "+f"((D)[1]), "+f"((D)[2]), "+f"((D)[3])            \
        : "r"((A)[0]), "r"((A)[1]), "r"((A)[2]), "r"((A)[3]),               \
          "r"(B0), "r"(B1))

static __device__ __forceinline__ void cp16(uint32_t dst, const void* src,
                                            bool v) {
    int sz = v ? 16 : 0;   // sz=0 -> zero-fill 16B, no gmem read
    asm volatile("cp.async.cg.shared.global [%0], [%1], 16, %2;"
                 :: "r"(dst), "l"(src), "r"(sz));
}
template <int N>
static __device__ __forceinline__ void cpwait() {
    asm volatile("cp.async.wait_group %0;" :: "n"(N) : "memory");
}
static __device__ __forceinline__ uint32_t smem_u32(const void* p) {
    uint32_t a;
    asm("{ .reg .u64 t; cvta.to.shared.u64 t, %1; cvt.u32.u64 %0, t; }"
        : "=r"(a) : "l"(p));
    return a;
}

// stage one k-chunk: 6 bf16 tiles [128 rows x 32 k] -> padded smem
static __device__ __forceinline__ void stage_chunk(
    uint32_t bufaddr, int tid, int b, int y0, int l0, int k0)
{
    const __nv_bfloat16* srcs[6] = {
        g_uh + (size_t)y0 * Dn, g_ul + (size_t)y0 * Dn,
        g_fh + (size_t)y0 * Dn, g_fl + (size_t)y0 * Dn,
        g_xh + ((size_t)b * Ln + l0) * Dn,
        g_xl + ((size_t)b * Ln + l0) * Dn };
#pragma unroll
    for (int sub = 0; sub < 6; sub++) {
        const __nv_bfloat16* src = srcs[sub];
        const int lim = (sub < 4) ? (Yn - y0) : (Ln - l0);
#pragma unroll
        for (int j = 0; j < 2; j++) {
            int idx = tid + j * NT;              // 0..511 = 128 rows x 4 segs
            int r = idx >> 2, seg = idx & 3;     // seg = 16B (8 bf16)
            uint32_t doff = (uint32_t)(r * SW + seg * 4) * 4u;
            cp16(bufaddr + sub * TILEW * 4 + doff,
                 src + (size_t)r * Dn + k0 + seg * 8, r < lim);
        }
    }
    asm volatile("cp.async.commit_group;" ::: "memory");
}

__global__ __launch_bounds__(NT)
void attn_mma_kernel(const float* __restrict__ f_b, float* __restrict__ out)
{
    extern __shared__ float smem[];
    const uint32_t sbase = smem_u32(smem);
    const int tid  = threadIdx.x;
    const int lane = tid & 31;
    const int g    = lane >> 2;          // group id 0..7
    const int tg   = lane & 3;           // thread in group 0..3
    const int wid  = tid >> 5;
    const int wy   = wid >> 1;           // warp y index 0..3 (32 y each)
    const int wl   = wid & 1;            // warp l index 0..1 (64 l each)
    const int b    = blockIdx.y;
    const int y0   = blockIdx.x * YT;

    // running softmax sums for this thread's 4 y rows
    float ss[4] = {0.f, 0.f, 0.f, 0.f};
    float zz[4] = {0.f, 0.f, 0.f, 0.f};

    for (int t = 0; t < NTILES; t++) {
        const int l0 = t * LT;

        float dS[2][8][4], dT[2][8][4];
#pragma unroll
        for (int a = 0; a < 2; a++)
#pragma unroll
            for (int c = 0; c < 8; c++)
#pragma unroll
                for (int r = 0; r < 4; r++) { dS[a][c][r] = 0.f; dT[a][c][r] = 0.f; }

        stage_chunk(sbase, tid, b, y0, l0, 0);

        for (int ch = 0; ch < NCH; ch++) {
            if (ch + 1 < NCH)
                stage_chunk(sbase + ((ch + 1) & 1) * BUFW * 4, tid,
                            b, y0, l0, (ch + 1) * KC);
            if (ch + 1 < NCH) cpwait<1>(); else cpwait<0>();
            __syncthreads();

            const uint32_t* Uh = (const uint32_t*)smem + (ch & 1) * BUFW;
            const uint32_t* Ul = Uh + TILEW;
            const uint32_t* Fh = Ul + TILEW;
            const uint32_t* Fl = Fh + TILEW;
            const uint32_t* Xh = Fl + TILEW;
            const uint32_t* Xl = Xh + TILEW;

#pragma unroll
            for (int ka = 0; ka < 2; ka++) {        // two k16 steps per chunk
                const int kb = ka * 8;              // k-pair base
                // B fragments for the warp's 64 l (8 n-tiles), hi+lo
                uint32_t bh[8][2], bl[8][2];
#pragma unroll
                for (int c = 0; c < 8; c++) {
                    int rb = (wl * 64 + c * 8 + g) * SW + kb + tg;
                    bh[c][0] = Xh[rb]; bh[c][1] = Xh[rb + 4];
                    bl[c][0] = Xl[rb]; bl[c][1] = Xl[rb + 4];
                }
#pragma unroll
                for (int a = 0; a < 2; a++) {
                    int r0 = (wy * 32 + a * 16 + g) * SW + kb + tg;
                    uint32_t auh[4], aul[4], afh[4], afl[4];
                    auh[0] = Uh[r0];          auh[1] = Uh[r0 + 8 * SW];
                    auh[2] = Uh[r0 + 4];      auh[3] = Uh[r0 + 8 * SW + 4];
                    aul[0] = Ul[r0];          aul[1] = Ul[r0 + 8 * SW];
                    aul[2] = Ul[r0 + 4];      aul[3] = Ul[r0 + 8 * SW + 4];
                    afh[0] = Fh[r0];          afh[1] = Fh[r0 + 8 * SW];
                    afh[2] = Fh[r0 + 4];      afh[3] = Fh[r0 + 8 * SW + 4];
                    afl[0] = Fl[r0];          afl[1] = Fl[r0 + 8 * SW];
                    afl[2] = Fl[r0 + 4];      afl[3] = Fl[r0 + 8 * SW + 4];
#pragma unroll
                    for (int c = 0; c < 8; c++) {
                        // S += Uh*Xh + Uh*Xl + Ul*Xh
                        MMA(dS[a][c], auh, bh[c][0], bh[c][1]);
                        MMA(dS[a][c], auh, bl[c][0], bl[c][1]);
                        MMA(dS[a][c], aul, bh[c][0], bh[c][1]);
                        // T += Fh*Xh + Fh*Xl + Fl*Xh
                        MMA(dT[a][c], afh, bh[c][0], bh[c][1]);
                        MMA(dT[a][c], afh, bl[c][0], bl[c][1]);
                        MMA(dT[a][c], afl, bh[c][0], bh[c][1]);
                    }
                }
            }
            __syncthreads();
        }

        // epilogue: exp + weighted accumulate (regs only), mask padded l
#pragma unroll
        for (int a = 0; a < 2; a++)
#pragma unroll
            for (int c = 0; c < 8; c++)
#pragma unroll
                for (int r2 = 0; r2 < 2; r2++) {
                    int le = l0 + wl * 64 + c * 8 + 2 * tg;
                    float s0 = dS[a][c][r2 * 2],     t0 = dT[a][c][r2 * 2];
                    float s1 = dS[a][c][r2 * 2 + 1], t1 = dT[a][c][r2 * 2 + 1];
                    if (le < Ln)     { float e = __expf(s0); ss[a*2+r2] += e; zz[a*2+r2] += e * t0; }
                    if (le + 1 < Ln) { float e = __expf(s1); ss[a*2+r2] += e; zz[a*2+r2] += e * t1; }
                }
    }

    // reduce across the 4 lanes sharing each y row (tg dimension)
#pragma unroll
    for (int i = 0; i < 4; i++) {
        ss[i] += __shfl_xor_sync(0xffffffffu, ss[i], 1);
        ss[i] += __shfl_xor_sync(0xffffffffu, ss[i], 2);
        zz[i] += __shfl_xor_sync(0xffffffffu, zz[i], 1);
        zz[i] += __shfl_xor_sync(0xffffffffu, zz[i], 2);
    }

    // cross-warp (wl) reduction via smem (compute done; buffers reusable)
    __syncthreads();
    float* sred = smem;          // [2][128]
    float* zred = smem + 256;    // [2][128]
    if (tg == 0) {
#pragma unroll
        for (int i = 0; i < 4; i++) {
            int yl = wy * 32 + (i >> 1) * 16 + (i & 1) * 8 + g;
            sred[wl * 128 + yl] = ss[i];
            zred[wl * 128 + yl] = zz[i];
        }
    }
    __syncthreads();
    if (tid < 128) {
        int yg = y0 + tid;
        if (yg < Yn) {
            float s = sred[tid] + sred[128 + tid];
            float z = zred[tid] + zred[128 + tid];
            out[(size_t)b * Yn + yg] = z / s + f_b[yg];
        }
    }
}

// ---------------- prepass: fp32 -> bf16 hi/lo ----------------
static __device__ __forceinline__ void split2(float v, __nv_bfloat16* h,
                                              __nv_bfloat16* l) {
    __nv_bfloat16 hh = __float2bfloat16(v);
    *h = hh;
    *l = __float2bfloat16(v - __bfloat162float(hh));
}

__global__ void prep_w(const float* __restrict__ U, const float* __restrict__ F)
{
    const size_t n = (size_t)Yn * Dn;
    for (size_t i = (size_t)blockIdx.x * blockDim.x + threadIdx.x; i < n;
         i += (size_t)gridDim.x * blockDim.x) {
        split2(U[i], &g_uh[i], &g_ul[i]);
        split2(F[i], &g_fh[i], &g_fl[i]);
    }
}

__global__ void prep_x(const float* __restrict__ x)
{
    const size_t n = (size_t)Bn * Ln * Dn;
    for (size_t i = (size_t)blockIdx.x * blockDim.x + threadIdx.x; i < n;
         i += (size_t)gridDim.x * blockDim.x)
        split2(x[i], &g_xh[i], &g_xl[i]);
}

// mean BCE-with-logits; single block, fixed-order -> deterministic
__global__ void bce_kernel(const float* __restrict__ y,
                           const float* __restrict__ t,
                           float* __restrict__ loss_out, int n)
{
    __shared__ float red[1024];
    float acc = 0.f;
    for (int i = threadIdx.x; i < n; i += 1024) {
        float v  = y[i];
        float tt = t[i];
        acc += fmaxf(v, 0.f) - v * tt + log1pf(__expf(-fabsf(v)));
    }
    red[threadIdx.x] = acc;
    __syncthreads();
    for (int s = 512; s > 0; s >>= 1) {
        if (threadIdx.x < s) red[threadIdx.x] += red[threadIdx.x + s];
        __syncthreads();
    }
    if (threadIdx.x == 0) loss_out[0] = red[0] / (float)n;
}

extern "C" void kernel_launch(void* const* d_in, const int* in_sizes, int n_in,
                              void* d_out, int out_size)
{
    const float* x      = (const float*)d_in[0];
    const float* target = (const float*)d_in[1];
    // d_in[2] = text_inputs (unused)
    const float* U_w    = (const float*)d_in[3];
    const float* F_w    = (const float*)d_in[4];
    const float* f_b    = (const float*)d_in[5];
    float* out = (float*)d_out;

    cudaFuncSetAttribute(attn_mma_kernel,
                         cudaFuncAttributeMaxDynamicSharedMemorySize, SMEM_BYTES);

    prep_w<<<1024, 256>>>(U_w, F_w);
    prep_x<<<2048, 256>>>(x);

    dim3 grid((Yn + YT - 1) / YT, Bn);   // 70 x 8 = 560 CTAs
    attn_mma_kernel<<<grid, NT, SMEM_BYTES>>>(f_b, out);

    if (out_size > Bn * Yn)
        bce_kernel<<<1, 1024>>>(out, target, out + Bn * Yn, Bn * Yn);
}

// round 6
// speedup vs baseline: 4.9706x; 1.1474x over previous
#include <cuda_runtime.h>
#include <cuda_bf16.h>
#include <cstdint>

#define Bn 8
#define Ln 2500
#define Dn 512
#define Yn 8921
#define YT 128          // y per CTA
#define LT 128          // l per CTA tile
#define KC 64           // k per chunk (bf16 elems)
#define NCH (Dn / KC)   // 8 chunks
#define NTILES 20       // ceil(2500/128)
#define NT 256
#define ROWB 144                    // smem row stride bytes (64 bf16 + 8 pad)
#define TILE_BYTES (128 * ROWB)     // 18432
#define BUF_BYTES (6 * TILE_BYTES)  // 110592 : Uh Ul Fh Fl Xh Xl
#define SMEM_BYTES (2 * BUF_BYTES)  // 221184

// bf16 hi/lo scratch (device globals; no runtime alloc)
__device__ __nv_bfloat16 g_xh[(size_t)Bn * Ln * Dn];
__device__ __nv_bfloat16 g_xl[(size_t)Bn * Ln * Dn];
__device__ __nv_bfloat16 g_uh[(size_t)Yn * Dn];
__device__ __nv_bfloat16 g_ul[(size_t)Yn * Dn];
__device__ __nv_bfloat16 g_fh[(size_t)Yn * Dn];
__device__ __nv_bfloat16 g_fl[(size_t)Yn * Dn];

// mma.sync m16n8k16 bf16 (plain sm_80+ instruction)
#define MMA(D, A, B0, B1)                                                   \
    asm volatile(                                                           \
        "mma.sync.aligned.m16n8k16.row.col.f32.bf16.bf16.f32 "              \
        "{%0,%1,%2,%3}, {%4,%5,%6,%7}, {%8,%9}, {%0,%1,%2,%3};"             \
        : "+f"((D)[0]), "+f"((D)[1]), "+f"((D)[2]), "+f"((D)[3])            \
        : "r"((A)[0]), "r"((A)[1]), "r"((A)[2]), "r"((A)[3]),               \
          "r"(B0), "r"(B1))

#define LDSM4(R0, R1, R2, R3, addr)                                         \
    asm volatile(                                                           \
        "ldmatrix.sync.aligned.m8n8.x4.shared.b16 {%0,%1,%2,%3}, [%4];"     \
        : "=r"(R0), "=r"(R1), "=r"(R2), "=r"(R3) : "r"(addr))

static __device__ __forceinline__ void cp16(uint32_t dst, const void* src,
                                            bool v) {
    int sz = v ? 16 : 0;   // sz=0 -> zero-fill 16B, no gmem read
    asm volatile("cp.async.cg.shared.global [%0], [%1], 16, %2;"
                 :: "r"(dst), "l"(src), "r"(sz));
}
template <int N>
static __device__ __forceinline__ void cpwait() {
    asm volatile("cp.async.wait_group %0;" :: "n"(N) : "memory");
}
static __device__ __forceinline__ uint32_t smem_u32(const void* p) {
    uint32_t a;
    asm("{ .reg .u64 t; cvta.to.shared.u64 t, %1; cvt.u32.u64 %0, t; }"
        : "=r"(a) : "l"(p));
    return a;
}

// stage one k-chunk: 6 bf16 tiles [128 rows x 64 k] -> padded smem
static __device__ __forceinline__ void stage_chunk(
    uint32_t bufaddr, int tid, int b, int y0, int l0, int k0)
{
    const __nv_bfloat16* srcs[6] = {
        g_uh + (size_t)y0 * Dn, g_ul + (size_t)y0 * Dn,
        g_fh + (size_t)y0 * Dn, g_fl + (size_t)y0 * Dn,
        g_xh + ((size_t)b * Ln + l0) * Dn,
        g_xl + ((size_t)b * Ln + l0) * Dn };
#pragma unroll
    for (int sub = 0; sub < 6; sub++) {
        const __nv_bfloat16* src = srcs[sub];
        const int lim = (sub < 4) ? (Yn - y0) : (Ln - l0);
#pragma unroll
        for (int j = 0; j < 4; j++) {
            int idx = tid + j * NT;              // 0..1023 = 128 rows x 8 segs
            int r = idx >> 3, seg = idx & 7;     // seg = 16B (8 bf16)
            cp16(bufaddr + sub * TILE_BYTES + (uint32_t)(r * ROWB + seg * 16),
                 src + (size_t)r * Dn + k0 + seg * 8, r < lim);
        }
    }
    asm volatile("cp.async.commit_group;" ::: "memory");
}

__global__ __launch_bounds__(NT)
void attn_mma_kernel(const float* __restrict__ f_b, float* __restrict__ out)
{
    extern __shared__ float smem[];
    const uint32_t sbase = smem_u32(smem);
    const int tid  = threadIdx.x;
    const int lane = tid & 31;
    const int g    = lane >> 2;          // group id 0..7
    const int tg   = lane & 3;           // thread in group 0..3
    const int wid  = tid >> 5;
    const int wy   = wid >> 1;           // warp y index 0..3 (32 y each)
    const int wl   = wid & 1;            // warp l index 0..1 (64 l each)
    const int b    = blockIdx.y;
    const int y0   = blockIdx.x * YT;

    // ldmatrix per-lane address components (bytes)
    const int quad = lane >> 3, r8 = lane & 7;
    const uint32_t laneA = (uint32_t)((r8 + (quad & 1) * 8) * ROWB + (quad >> 1) * 16);
    const uint32_t laneB = (uint32_t)((r8 + (quad >> 1) * 8) * ROWB + (quad & 1) * 16);
    uint32_t aRow[2], bRow[4];
#pragma unroll
    for (int a = 0; a < 2; a++) aRow[a] = (uint32_t)((wy * 32 + a * 16) * ROWB) + laneA;
#pragma unroll
    for (int cp = 0; cp < 4; cp++) bRow[cp] = (uint32_t)((wl * 64 + cp * 16) * ROWB) + laneB;

    // running softmax sums for this thread's 4 y rows
    float ss[4] = {0.f, 0.f, 0.f, 0.f};
    float zz[4] = {0.f, 0.f, 0.f, 0.f};

    stage_chunk(sbase, tid, b, y0, 0, 0);   // tile 0, chunk 0 -> buf 0

    for (int t = 0; t < NTILES; t++) {
        const int l0 = t * LT;

        float dS[2][8][4], dT[2][8][4];
#pragma unroll
        for (int a = 0; a < 2; a++)
#pragma unroll
            for (int c = 0; c < 8; c++)
#pragma unroll
                for (int r = 0; r < 4; r++) { dS[a][c][r] = 0.f; dT[a][c][r] = 0.f; }

        for (int ch = 0; ch < NCH; ch++) {
            const bool last_all = (t == NTILES - 1) && (ch == NCH - 1);
            if (!last_all) {
                // prefetch next chunk (possibly next tile's chunk 0)
                int nl0 = (ch == NCH - 1) ? l0 + LT : l0;
                int nk0 = (ch == NCH - 1) ? 0 : (ch + 1) * KC;
                stage_chunk(sbase + ((ch + 1) & 1) * BUF_BYTES, tid, b, y0, nl0, nk0);
                cpwait<1>();
            } else {
                cpwait<0>();
            }
            __syncthreads();

            const uint32_t bufb = sbase + (ch & 1) * BUF_BYTES;

#pragma unroll
            for (int ka = 0; ka < 4; ka++) {        // four k16 steps
                const uint32_t kao = (uint32_t)(ka * 32);
                uint32_t auh[2][4], aul[2][4], afh[2][4], afl[2][4];
#pragma unroll
                for (int a = 0; a < 2; a++) {
                    uint32_t ab = bufb + aRow[a] + kao;
                    LDSM4(auh[a][0], auh[a][1], auh[a][2], auh[a][3], ab);
                    LDSM4(aul[a][0], aul[a][1], aul[a][2], aul[a][3], ab + TILE_BYTES);
                    LDSM4(afh[a][0], afh[a][1], afh[a][2], afh[a][3], ab + 2 * TILE_BYTES);
                    LDSM4(afl[a][0], afl[a][1], afl[a][2], afl[a][3], ab + 3 * TILE_BYTES);
                }
                uint32_t bh[8][2], bl[8][2];
#pragma unroll
                for (int cp = 0; cp < 4; cp++) {
                    uint32_t bb = bufb + 4 * TILE_BYTES + bRow[cp] + kao;
                    LDSM4(bh[2*cp][0], bh[2*cp][1], bh[2*cp+1][0], bh[2*cp+1][1], bb);
                    LDSM4(bl[2*cp][0], bl[2*cp][1], bl[2*cp+1][0], bl[2*cp+1][1],
                          bb + TILE_BYTES);
                }
#pragma unroll
                for (int a = 0; a < 2; a++) {
#pragma unroll
                    for (int c = 0; c < 8; c++) {
                        // S += Uh*Xh + Uh*Xl + Ul*Xh
                        MMA(dS[a][c], auh[a], bh[c][0], bh[c][1]);
                        MMA(dS[a][c], auh[a], bl[c][0], bl[c][1]);
                        MMA(dS[a][c], aul[a], bh[c][0], bh[c][1]);
                        // T += Fh*Xh + Fh*Xl + Fl*Xh
                        MMA(dT[a][c], afh[a], bh[c][0], bh[c][1]);
                        MMA(dT[a][c], afh[a], bl[c][0], bl[c][1]);
                        MMA(dT[a][c], afl[a], bh[c][0], bh[c][1]);
                    }
                }
            }
            __syncthreads();   // release buf (ch&1) for the stage at iter ch+1
        }

        // epilogue (regs only) — overlaps the in-flight prefetch of next tile
#pragma unroll
        for (int a = 0; a < 2; a++)
#pragma unroll
            for (int c = 0; c < 8; c++)
#pragma unroll
                for (int r2 = 0; r2 < 2; r2++) {
                    int le = l0 + wl * 64 + c * 8 + 2 * tg;
                    float s0 = dS[a][c][r2 * 2],     t0 = dT[a][c][r2 * 2];
                    float s1 = dS[a][c][r2 * 2 + 1], t1 = dT[a][c][r2 * 2 + 1];
                    if (le < Ln)     { float e = __expf(s0); ss[a*2+r2] += e; zz[a*2+r2] += e * t0; }
                    if (le + 1 < Ln) { float e = __expf(s1); ss[a*2+r2] += e; zz[a*2+r2] += e * t1; }
                }
    }

    // reduce across the 4 lanes sharing each y row (tg dimension)
#pragma unroll
    for (int i = 0; i < 4; i++) {
        ss[i] += __shfl_xor_sync(0xffffffffu, ss[i], 1);
        ss[i] += __shfl_xor_sync(0xffffffffu, ss[i], 2);
        zz[i] += __shfl_xor_sync(0xffffffffu, zz[i], 1);
        zz[i] += __shfl_xor_sync(0xffffffffu, zz[i], 2);
    }

    // cross-warp (wl) reduction via smem (all staging finished by now)
    __syncthreads();
    float* sred = smem;          // [2][128]
    float* zred = smem + 256;    // [2][128]
    if (tg == 0) {
#pragma unroll
        for (int i = 0; i < 4; i++) {
            int yl = wy * 32 + (i >> 1) * 16 + (i & 1) * 8 + g;
            sred[wl * 128 + yl] = ss[i];
            zred[wl * 128 + yl] = zz[i];
        }
    }
    __syncthreads();
    if (tid < 128) {
        int yg = y0 + tid;
        if (yg < Yn) {
            float s = sred[tid] + sred[128 + tid];
            float z = zred[tid] + zred[128 + tid];
            out[(size_t)b * Yn + yg] = z / s + f_b[yg];
        }
    }
}

// ---------------- prepass: fp32 -> bf16 hi/lo ----------------
static __device__ __forceinline__ void split2(float v, __nv_bfloat16* h,
                                              __nv_bfloat16* l) {
    __nv_bfloat16 hh = __float2bfloat16(v);
    *h = hh;
    *l = __float2bfloat16(v - __bfloat162float(hh));
}

__global__ void prep_w(const float* __restrict__ U, const float* __restrict__ F)
{
    const size_t n = (size_t)Yn * Dn;
    for (size_t i = (size_t)blockIdx.x * blockDim.x + threadIdx.x; i < n;
         i += (size_t)gridDim.x * blockDim.x) {
        split2(U[i], &g_uh[i], &g_ul[i]);
        split2(F[i], &g_fh[i], &g_fl[i]);
    }
}

__global__ void prep_x(const float* __restrict__ x)
{
    const size_t n = (size_t)Bn * Ln * Dn;
    for (size_t i = (size_t)blockIdx.x * blockDim.x + threadIdx.x; i < n;
         i += (size_t)gridDim.x * blockDim.x)
        split2(x[i], &g_xh[i], &g_xl[i]);
}

// mean BCE-with-logits; single block, fixed-order -> deterministic
__global__ void bce_kernel(const float* __restrict__ y,
                           const float* __restrict__ t,
                           float* __restrict__ loss_out, int n)
{
    __shared__ float red[1024];
    float acc = 0.f;
    for (int i = threadIdx.x; i < n; i += 1024) {
        float v  = y[i];
        float tt = t[i];
        acc += fmaxf(v, 0.f) - v * tt + log1pf(__expf(-fabsf(v)));
    }
    red[threadIdx.x] = acc;
    __syncthreads();
    for (int s = 512; s > 0; s >>= 1) {
        if (threadIdx.x < s) red[threadIdx.x] += red[threadIdx.x + s];
        __syncthreads();
    }
    if (threadIdx.x == 0) loss_out[0] = red[0] / (float)n;
}

extern "C" void kernel_launch(void* const* d_in, const int* in_sizes, int n_in,
                              void* d_out, int out_size)
{
    const float* x      = (const float*)d_in[0];
    const float* target = (const float*)d_in[1];
    // d_in[2] = text_inputs (unused)
    const float* U_w    = (const float*)d_in[3];
    const float* F_w    = (const float*)d_in[4];
    const float* f_b    = (const float*)d_in[5];
    float* out = (float*)d_out;

    cudaFuncSetAttribute(attn_mma_kernel,
                         cudaFuncAttributeMaxDynamicSharedMemorySize, SMEM_BYTES);

    prep_w<<<1024, 256>>>(U_w, F_w);
    prep_x<<<2048, 256>>>(x);

    dim3 grid((Yn + YT - 1) / YT, Bn);   // 70 x 8 = 560 CTAs
    attn_mma_kernel<<<grid, NT, SMEM_BYTES>>>(f_b, out);

    if (out_size > Bn * Yn)
        bce_kernel<<<1, 1024>>>(out, target, out + Bn * Yn, Bn * Yn);
}